// round 11
// baseline (speedup 1.0000x reference)
#include <cuda_runtime.h>
#include <cuda_bf16.h>
#include <cstdint>
#include <math.h>

#define NN 100000
#define EE 1000000
#define BM 64
#define THREADS 1024
#define NBLK ((NN + BM - 1) / BM)      // 1563
#define GRID_PERSIST 148

#define BP 144
#define XP 272

// smem byte offsets
#define SM_B_HI   0
#define SM_B_LO   73728
#define SM_XHI    147456
#define SM_XLO    182272
#define SM_ROWSUM 217088               // float[2][64]
#define SM_CTR    217600               // int[2]
#define SM_TOTAL  217728

typedef unsigned int u32;
typedef unsigned long long u64;

// Scratch
__device__ int  g_cnt[NN];
__device__ int  g_off[NN];
__device__ int  g_cur[NN];
__device__ int  g_total;
__device__ int2 g_meta[EE];
__device__ __align__(16) __nv_bfloat16 g_Bhi[256 * BP];
__device__ __align__(16) __nv_bfloat16 g_Blo[256 * BP];

// ---------------------------------------------------------------------------
// CSR build (hist also performs the B prep so the fused kernel is launch #5)
// ---------------------------------------------------------------------------
__global__ void hist_prep_kernel(const int* __restrict__ dst,
                                 int* __restrict__ cnt,
                                 const float* __restrict__ W1,
                                 const float* __restrict__ W2,
                                 __nv_bfloat16* __restrict__ bhi,
                                 __nv_bfloat16* __restrict__ blo)
{
    int e = blockIdx.x * blockDim.x + threadIdx.x;
    if (e < EE) atomicAdd(&cnt[__ldg(dst + e)], 1);
    if (e < 256 * 128) {
        int k = e >> 7;
        int n = e & 127;
        float v = (k < 128) ? __ldg(W1 + k * 128 + n) : __ldg(W2 + (k - 128) * 128 + n);
        __nv_bfloat16 h = __float2bfloat16(v);
        bhi[k * BP + n] = h;
        blo[k * BP + n] = __float2bfloat16(v - __bfloat162float(h));
    }
}

__global__ void alloc_kernel(const int* __restrict__ cnt,
                             int* __restrict__ off,
                             int* __restrict__ cur,
                             int* __restrict__ total)
{
    int i = blockIdx.x * blockDim.x + threadIdx.x;
    if (i < NN) {
        int o = atomicAdd(total, cnt[i]);
        off[i] = o;
        cur[i] = o;
    }
}

__global__ void scatter_kernel(const int* __restrict__ src,
                               const int* __restrict__ dst,
                               const float* __restrict__ norm,
                               int* __restrict__ cur,
                               int2* __restrict__ meta)
{
    int e = blockIdx.x * blockDim.x + threadIdx.x;
    if (e >= EE) return;
    int s = __ldg(src + e);
    int d = __ldg(dst + e);
    float w = __ldg(norm + s) * __ldg(norm + d);
    int pos = atomicAdd(&cur[d], 1);
    meta[pos] = make_int2(s, __float_as_int(w));
}

// ---------------------------------------------------------------------------
// PTX helpers
// ---------------------------------------------------------------------------
__device__ __forceinline__ u32 smem_u32_of(const void* p)
{
    u32 a;
    asm("{ .reg .u64 t; cvta.to.shared.u64 t, %1; cvt.u32.u64 %0, t; }"
        : "=r"(a) : "l"(p));
    return a;
}
__device__ __forceinline__ void cp_async16(u32 dst, const void* src)
{
    asm volatile("cp.async.cg.shared.global [%0], [%1], 16;"
                 :: "r"(dst), "l"(src) : "memory");
}
__device__ __forceinline__ void ldsm_x4(u32& r0, u32& r1, u32& r2, u32& r3, u32 addr)
{
    asm volatile("ldmatrix.sync.aligned.m8n8.x4.shared.b16 {%0,%1,%2,%3}, [%4];"
                 : "=r"(r0), "=r"(r1), "=r"(r2), "=r"(r3) : "r"(addr));
}
__device__ __forceinline__ void ldsm_x4_t(u32& r0, u32& r1, u32& r2, u32& r3, u32 addr)
{
    asm volatile("ldmatrix.sync.aligned.m8n8.x4.trans.shared.b16 {%0,%1,%2,%3}, [%4];"
                 : "=r"(r0), "=r"(r1), "=r"(r2), "=r"(r3) : "r"(addr));
}
__device__ __forceinline__ void mma16816(float* c, u32 a0, u32 a1, u32 a2, u32 a3,
                                         u32 b0, u32 b1)
{
    asm volatile(
        "mma.sync.aligned.m16n8k16.row.col.f32.bf16.bf16.f32 "
        "{%0,%1,%2,%3}, {%4,%5,%6,%7}, {%8,%9}, {%0,%1,%2,%3};"
        : "+f"(c[0]), "+f"(c[1]), "+f"(c[2]), "+f"(c[3])
        : "r"(a0), "r"(a1), "r"(a2), "r"(a3), "r"(b0), "r"(b1));
}
__device__ __forceinline__ u32 pack_hi(float x, float y)
{
    unsigned short b0 = __bfloat16_as_ushort(__float2bfloat16(x));
    unsigned short b1 = __bfloat16_as_ushort(__float2bfloat16(y));
    return (u32)b0 | ((u32)b1 << 16);
}
__device__ __forceinline__ u32 pack_lo(float x, float y)
{
    float hx = __bfloat162float(__float2bfloat16(x));
    float hy = __bfloat162float(__float2bfloat16(y));
    unsigned short b0 = __bfloat16_as_ushort(__float2bfloat16(x - hx));
    unsigned short b1 = __bfloat16_as_ushort(__float2bfloat16(y - hy));
    return (u32)b0 | ((u32)b1 << 16);
}

// ---------------------------------------------------------------------------
// Persistent fused kernel, 2 barriers/tile, node work-stealing
// ---------------------------------------------------------------------------
__global__ void __launch_bounds__(THREADS, 1)
fused_kernel(const float4* __restrict__ ego,
             const int*   __restrict__ off,
             const int*   __restrict__ cnt,
             const int2*  __restrict__ meta,
             float*       __restrict__ out)
{
    extern __shared__ char smem[];
    const u32 smem_base = smem_u32_of(smem);
    float* rowsum = (float*)(smem + SM_ROWSUM);   // [2][64]
    int*   ctr    = (int*)(smem + SM_CTR);        // [2]

    const int tid  = threadIdx.x;
    const int lane = tid & 31;
    const int warp = tid >> 5;

    // ---- 0) one-time: load Bhi/Blo into smem
    {
        const char* shi = (const char*)g_Bhi;
        const char* slo = (const char*)g_Blo;
        #pragma unroll
        for (int i = 0; i < 5; ++i) {
            int m = tid + i * THREADS;
            if (m < 4608) {
                cp_async16(smem_base + SM_B_HI + m * 16, shi + m * 16);
                cp_async16(smem_base + SM_B_LO + m * 16, slo + m * 16);
            }
        }
        asm volatile("cp.async.commit_group;" ::: "memory");
        asm volatile("cp.async.wait_group 0;" ::: "memory");
    }
    if (tid < 2 * BM) rowsum[tid] = 0.f;
    if (tid < 2) ctr[tid] = 0;
    __syncthreads();

    // GEMM constants: warp grid 4m x 8n; warp tile 16m x 16n
    const int m0 = (warp >> 3) * 16;
    const int n0 = (warp & 7) * 16;
    const u32 a_row = m0 + (lane & 15);
    const u32 a_col = (lane >> 4) * 8;
    const u32 aHiBase = smem_base + SM_XHI + a_row * (XP * 2) + a_col * 2;
    const u32 aLoBase = smem_base + SM_XLO + a_row * (XP * 2) + a_col * 2;
    const u32 b_krow = (lane & 7) + ((lane >> 3) & 1) * 8;
    const u32 b_ncol = (lane >> 4) * 8;
    const u32 bHiBase = smem_base + SM_B_HI + b_krow * (BP * 2) + (n0 + b_ncol) * 2;
    const u32 bLoBase = smem_base + SM_B_LO + b_krow * (BP * 2) + (n0 + b_ncol) * 2;
    const int r0 = m0 + (lane >> 2);
    const int r1 = r0 + 8;

    int par = 0;
    for (int tile = blockIdx.x; tile < NBLK; tile += GRID_PERSIST, par ^= 1) {
        const int rowBase = tile * BM;

        // ---- 1) aggregate: steal nodes until tile exhausted
        for (;;) {
            int r;
            if (lane == 0) r = atomicAdd(&ctr[par], 1);
            r = __shfl_sync(0xffffffffu, r, 0);
            if (r >= BM) break;

            int node = rowBase + r;
            bool valid = node < NN;

            float4 hd = valid ? __ldg(ego + (size_t)node * 32 + lane)
                              : make_float4(0.f, 0.f, 0.f, 0.f);
            float4 a = hd;
            float4 b = make_float4(0.f, 0.f, 0.f, 0.f);

            int n  = valid ? __ldg(cnt + node) : 0;
            int e0 = valid ? __ldg(off + node) : 0;

            for (int c = 0; c < n; c += 32) {
                int lim = min(32, n - c);
                int2 mm = (lane < lim) ? __ldg(meta + e0 + c + lane) : make_int2(0, 0);
                int j = 0;
                for (; j + 4 <= lim; j += 4) {
                    int   s0 = __shfl_sync(0xffffffffu, mm.x, j + 0);
                    int   s1 = __shfl_sync(0xffffffffu, mm.x, j + 1);
                    int   s2 = __shfl_sync(0xffffffffu, mm.x, j + 2);
                    int   s3 = __shfl_sync(0xffffffffu, mm.x, j + 3);
                    float w0 = __int_as_float(__shfl_sync(0xffffffffu, mm.y, j + 0));
                    float w1 = __int_as_float(__shfl_sync(0xffffffffu, mm.y, j + 1));
                    float w2 = __int_as_float(__shfl_sync(0xffffffffu, mm.y, j + 2));
                    float w3 = __int_as_float(__shfl_sync(0xffffffffu, mm.y, j + 3));
                    float4 h0 = __ldg(ego + (size_t)s0 * 32 + lane);
                    float4 h1 = __ldg(ego + (size_t)s1 * 32 + lane);
                    float4 h2 = __ldg(ego + (size_t)s2 * 32 + lane);
                    float4 h3 = __ldg(ego + (size_t)s3 * 32 + lane);
                    float t;
                    t = w0 * h0.x; a.x += t; b.x = fmaf(t, hd.x, b.x);
                    t = w0 * h0.y; a.y += t; b.y = fmaf(t, hd.y, b.y);
                    t = w0 * h0.z; a.z += t; b.z = fmaf(t, hd.z, b.z);
                    t = w0 * h0.w; a.w += t; b.w = fmaf(t, hd.w, b.w);
                    t = w1 * h1.x; a.x += t; b.x = fmaf(t, hd.x, b.x);
                    t = w1 * h1.y; a.y += t; b.y = fmaf(t, hd.y, b.y);
                    t = w1 * h1.z; a.z += t; b.z = fmaf(t, hd.z, b.z);
                    t = w1 * h1.w; a.w += t; b.w = fmaf(t, hd.w, b.w);
                    t = w2 * h2.x; a.x += t; b.x = fmaf(t, hd.x, b.x);
                    t = w2 * h2.y; a.y += t; b.y = fmaf(t, hd.y, b.y);
                    t = w2 * h2.z; a.z += t; b.z = fmaf(t, hd.z, b.z);
                    t = w2 * h2.w; a.w += t; b.w = fmaf(t, hd.w, b.w);
                    t = w3 * h3.x; a.x += t; b.x = fmaf(t, hd.x, b.x);
                    t = w3 * h3.y; a.y += t; b.y = fmaf(t, hd.y, b.y);
                    t = w3 * h3.z; a.z += t; b.z = fmaf(t, hd.z, b.z);
                    t = w3 * h3.w; a.w += t; b.w = fmaf(t, hd.w, b.w);
                }
                for (; j < lim; ++j) {
                    int   s0 = __shfl_sync(0xffffffffu, mm.x, j);
                    float w0 = __int_as_float(__shfl_sync(0xffffffffu, mm.y, j));
                    float4 h0 = __ldg(ego + (size_t)s0 * 32 + lane);
                    float t;
                    t = w0 * h0.x; a.x += t; b.x = fmaf(t, hd.x, b.x);
                    t = w0 * h0.y; a.y += t; b.y = fmaf(t, hd.y, b.y);
                    t = w0 * h0.z; a.z += t; b.z = fmaf(t, hd.z, b.z);
                    t = w0 * h0.w; a.w += t; b.w = fmaf(t, hd.w, b.w);
                }
            }

            u32* xh = (u32*)(smem + SM_XHI + (size_t)r * (XP * 2));
            u32* xl = (u32*)(smem + SM_XLO + (size_t)r * (XP * 2));
            xh[lane * 2 + 0]  = pack_hi(a.x, a.y);
            xh[lane * 2 + 1]  = pack_hi(a.z, a.w);
            xh[64 + lane * 2] = pack_hi(b.x, b.y);
            xh[65 + lane * 2] = pack_hi(b.z, b.w);
            xl[lane * 2 + 0]  = pack_lo(a.x, a.y);
            xl[lane * 2 + 1]  = pack_lo(a.z, a.w);
            xl[64 + lane * 2] = pack_lo(b.x, b.y);
            xl[65 + lane * 2] = pack_lo(b.z, b.w);
        }
        __syncthreads();                 // bar1: X complete, prev rowsum reads done

        // prepare NEXT tile's steal counter and rowsum (parity^1)
        if (tid == 0) ctr[par ^ 1] = 0;
        if (tid < BM) rowsum[(par ^ 1) * BM + tid] = 0.f;

        // ---- 2) GEMM: warp tile 16m x 16n; K=256, split-2
        float acc[2][4];
        #pragma unroll
        for (int i = 0; i < 2; ++i)
            #pragma unroll
            for (int j = 0; j < 4; ++j) acc[i][j] = 0.f;

        #pragma unroll 4
        for (int ks = 0; ks < 16; ++ks) {
            const u32 kOffA = ks * 32;
            const u32 kOffB = ks * 16 * (BP * 2);
            u32 ah0, ah1, ah2, ah3, al0, al1, al2, al3;
            ldsm_x4(ah0, ah1, ah2, ah3, aHiBase + kOffA);
            ldsm_x4(al0, al1, al2, al3, aLoBase + kOffA);

            u32 bh0, bh1, bh2, bh3, bl0, bl1, bl2, bl3;
            ldsm_x4_t(bh0, bh1, bh2, bh3, bHiBase + kOffB);
            ldsm_x4_t(bl0, bl1, bl2, bl3, bLoBase + kOffB);
            mma16816(acc[0], ah0, ah1, ah2, ah3, bh0, bh1);
            mma16816(acc[0], ah0, ah1, ah2, ah3, bl0, bl1);
            mma16816(acc[0], al0, al1, al2, al3, bh0, bh1);
            mma16816(acc[1], ah0, ah1, ah2, ah3, bh2, bh3);
            mma16816(acc[1], ah0, ah1, ah2, ah3, bl2, bl3);
            mma16816(acc[1], al0, al1, al2, al3, bh2, bh3);
        }

        // ---- 3) leaky relu + per-row sumsq partials into rowsum[par]
        float p0 = 0.f, p1 = 0.f;
        #pragma unroll
        for (int nt = 0; nt < 2; ++nt) {
            #pragma unroll
            for (int j = 0; j < 4; ++j) {
                float v = acc[nt][j];
                v = (v >= 0.f) ? v : 0.2f * v;
                acc[nt][j] = v;
                if (j < 2) p0 = fmaf(v, v, p0);
                else       p1 = fmaf(v, v, p1);
            }
        }
        p0 += __shfl_xor_sync(0xffffffffu, p0, 1);
        p0 += __shfl_xor_sync(0xffffffffu, p0, 2);
        p1 += __shfl_xor_sync(0xffffffffu, p1, 1);
        p1 += __shfl_xor_sync(0xffffffffu, p1, 2);
        if ((lane & 3) == 0) {
            atomicAdd(rowsum + par * BM + r0, p0);
            atomicAdd(rowsum + par * BM + r1, p1);
        }
        __syncthreads();                 // bar2: rowsum complete, X reads done

        // ---- 4) scale + store (no trailing barrier; flows into next aggregate)
        const float inv0 = 1.0f / fmaxf(sqrtf(rowsum[par * BM + r0]), 1e-12f);
        const float inv1 = 1.0f / fmaxf(sqrtf(rowsum[par * BM + r1]), 1e-12f);
        float2* out2 = (float2*)out;
        const int g0 = rowBase + r0;
        const int g1 = rowBase + r1;
        const int colh = (n0 + (lane & 3) * 2) >> 1;
        #pragma unroll
        for (int nt = 0; nt < 2; ++nt) {
            int c2 = colh + nt * 4;
            if (g0 < NN)
                out2[(size_t)g0 * 64 + c2] = make_float2(acc[nt][0] * inv0, acc[nt][1] * inv0);
            if (g1 < NN)
                out2[(size_t)g1 * 64 + c2] = make_float2(acc[nt][2] * inv1, acc[nt][3] * inv1);
        }
    }
}

// ---------------------------------------------------------------------------
// Launch
// ---------------------------------------------------------------------------
extern "C" void kernel_launch(void* const* d_in, const int* in_sizes, int n_in,
                              void* d_out, int out_size)
{
    const float* ego  = (const float*)d_in[0];
    const float* norm = (const float*)d_in[1];
    const int*   src  = (const int*)d_in[2];
    const int*   dst  = (const int*)d_in[3];
    const float* W1   = (const float*)d_in[4];
    const float* W2   = (const float*)d_in[5];
    float* out = (float*)d_out;

    int*  cnt;   cudaGetSymbolAddress((void**)&cnt,   g_cnt);
    int*  off;   cudaGetSymbolAddress((void**)&off,   g_off);
    int*  cur;   cudaGetSymbolAddress((void**)&cur,   g_cur);
    int*  total; cudaGetSymbolAddress((void**)&total, g_total);
    int2* meta;  cudaGetSymbolAddress((void**)&meta,  g_meta);
    __nv_bfloat16* bhi; cudaGetSymbolAddress((void**)&bhi, g_Bhi);
    __nv_bfloat16* blo; cudaGetSymbolAddress((void**)&blo, g_Blo);

    cudaMemsetAsync(cnt, 0, NN * sizeof(int));
    cudaMemsetAsync(total, 0, sizeof(int));
    hist_prep_kernel<<<(EE + 255) / 256, 256>>>(dst, cnt, W1, W2, bhi, blo);
    alloc_kernel<<<(NN + 255) / 256, 256>>>(cnt, off, cur, total);
    scatter_kernel<<<(EE + 255) / 256, 256>>>(src, dst, norm, cur, meta);

    cudaFuncSetAttribute(fused_kernel,
                         cudaFuncAttributeMaxDynamicSharedMemorySize, SM_TOTAL);
    fused_kernel<<<GRID_PERSIST, THREADS, SM_TOTAL>>>(
        (const float4*)ego, off, cnt, meta, out);
}